// round 1
// baseline (speedup 1.0000x reference)
#include <cuda_runtime.h>
#include <math.h>

#define NN    256
#define FEATD 1024
#define HIDR  256
#define HEADS 4
#define GCH   256
#define H1DIM 1024   // HEADS*GCH
#define OUTD  21
#define TOPK  3
#define E_TOT (NN*TOPK + NN)   // 1024 edges

// ---------------- scratch (device globals; no allocation allowed) ----------
__device__ float g_A[NN*HIDR];
__device__ float g_B[NN*HIDR];
__device__ float g_rel[NN*NN];
__device__ int   g_top[NN*TOPK];
__device__ int   g_src[E_TOT], g_tgt[E_TOT];
__device__ int   g_off[NN+1];
__device__ int   g_inc[E_TOT];
__device__ float g_h1[NN*H1DIM];
__device__ float g_ss1[NN*HEADS], g_ds1[NN*HEADS];
__device__ float g_x1[NN*H1DIM];
__device__ float g_h2[NN*OUTD];
__device__ float g_ss2[NN], g_ds2[NN];

// read a scalar that may have been serialized as int32 or float32
__device__ __forceinline__ float read_dim(const void* p) {
    int iv = *(const int*)p;
    if (iv > 0 && iv < 100000) return (float)iv;
    return *(const float*)p;
}

// ---------------- K1: A = F @ W_fc1[0:1024], B = F @ W_fc1[1024:2048] ------
__global__ void k_ab(const float* __restrict__ feat, const float* __restrict__ Wfc1) {
    __shared__ float sA[16][16];
    __shared__ float sW[16][17];
    const float* W = Wfc1 + (size_t)blockIdx.z * FEATD * HIDR;
    int row = blockIdx.y * 16 + threadIdx.y;
    int col = blockIdx.x * 16 + threadIdx.x;
    float acc = 0.f;
    for (int k0 = 0; k0 < FEATD; k0 += 16) {
        sA[threadIdx.y][threadIdx.x] = feat[row * FEATD + k0 + threadIdx.x];
        sW[threadIdx.y][threadIdx.x] = W[(size_t)(k0 + threadIdx.y) * HIDR + col];
        __syncthreads();
#pragma unroll
        for (int kk = 0; kk < 16; kk++)
            acc += sA[threadIdx.y][kk] * sW[kk][threadIdx.x];
        __syncthreads();
    }
    float* dst = blockIdx.z ? g_B : g_A;
    dst[row * HIDR + col] = acc;
}

// ---------------- K2: rel[i,j] = relu(A[i]+B[j]+geom@Wg+b1) . W_fc2 + b2 ---
__global__ void k_rel(const float* __restrict__ boxes,
                      const float* __restrict__ Wfc1,
                      const float* __restrict__ bfc1,
                      const float* __restrict__ Wfc2,
                      const float* __restrict__ bfc2) {
    int p    = blockIdx.x * 8 + (threadIdx.x >> 5);
    int lane = threadIdx.x & 31;
    int i = p >> 8, j = p & 255;
    float g0 = fabsf(boxes[i*4+0] - boxes[j*4+0]);
    float g1 = fabsf(boxes[i*4+1] - boxes[j*4+1]);
    float g2 = fabsf(boxes[i*4+2] - boxes[j*4+2]);
    float g3 = fabsf(boxes[i*4+3] - boxes[j*4+3]);
    const float* Wg = Wfc1 + (size_t)2 * FEATD * HIDR;  // rows 2048..2051
    float acc = 0.f;
    for (int c = lane; c < HIDR; c += 32) {
        float v = g_A[i*HIDR+c] + g_B[j*HIDR+c] + bfc1[c]
                + g0 * Wg[c] + g1 * Wg[HIDR + c]
                + g2 * Wg[2*HIDR + c] + g3 * Wg[3*HIDR + c];
        v = fmaxf(v, 0.f);
        acc += v * Wfc2[c];
    }
#pragma unroll
    for (int o = 16; o; o >>= 1) acc += __shfl_down_sync(0xffffffffu, acc, o);
    if (!lane) g_rel[p] = acc + bfc2[0];
}

// ---------------- K3: per-row top-4, drop first -> g_top[i][0..2] ----------
__global__ void k_topk() {
    int i = blockIdx.x, t = threadIdx.x;
    __shared__ float v[NN];
    __shared__ float rv[NN];
    __shared__ int   ri[NN];
    v[t] = g_rel[i * NN + t];
    __syncthreads();
    for (int sel = 0; sel < TOPK + 1; sel++) {
        rv[t] = v[t]; ri[t] = t;
        __syncthreads();
        for (int s = 128; s; s >>= 1) {
            if (t < s) {
                float a = rv[t], b = rv[t + s];
                // larger value wins; ties -> smaller index (lax.top_k semantics)
                if (b > a || (b == a && ri[t + s] < ri[t])) { rv[t] = b; ri[t] = ri[t + s]; }
            }
            __syncthreads();
        }
        int best = ri[0];
        if (sel > 0 && t == 0) g_top[i * TOPK + sel - 1] = best;
        if (t == best) v[t] = -INFINITY;
        __syncthreads();
    }
}

// ---------------- K4: edge list + CSR of incoming edges (deterministic) ----
__global__ void k_edges() {
    int t = threadIdx.x;   // one block of 256
    __shared__ int counts[NN];
#pragma unroll
    for (int j = 0; j < TOPK; j++) {
        g_src[t * TOPK + j] = t;
        g_tgt[t * TOPK + j] = g_top[t * TOPK + j];
    }
    g_src[NN * TOPK + t] = t;
    g_tgt[NN * TOPK + t] = t;
    counts[t] = 0;
    __syncthreads();
    if (t == 0) {
        for (int e = 0; e < E_TOT; e++) counts[g_tgt[e]]++;
        int run = 0;
        for (int n = 0; n < NN; n++) { g_off[n] = run; run += counts[n]; counts[n] = g_off[n]; }
        g_off[NN] = run;
        for (int e = 0; e < E_TOT; e++) { int tt = g_tgt[e]; g_inc[counts[tt]++] = e; }
    }
}

// ---------------- K5: h1 = [features | geomn] @ W1 -------------------------
__global__ void k_gemm1(const float* __restrict__ feat,
                        const float* __restrict__ boxes,
                        const float* __restrict__ W1,
                        const void* img_h, const void* img_w) {
    __shared__ float sA[16][16];
    __shared__ float sW[16][17];
    int n = blockIdx.y * 16 + threadIdx.y;
    int o = blockIdx.x * 16 + threadIdx.x;
    float acc = 0.f;
    for (int k0 = 0; k0 < FEATD; k0 += 16) {
        sA[threadIdx.y][threadIdx.x] = feat[n * FEATD + k0 + threadIdx.x];
        sW[threadIdx.y][threadIdx.x] = W1[(size_t)(k0 + threadIdx.y) * H1DIM + o];
        __syncthreads();
#pragma unroll
        for (int kk = 0; kk < 16; kk++)
            acc += sA[threadIdx.y][kk] * sW[kk][threadIdx.x];
        __syncthreads();
    }
    float fw = read_dim(img_w), fh = read_dim(img_h);
    float b0 = boxes[n*4+0] / fw, b1 = boxes[n*4+1] / fh;
    float b2 = boxes[n*4+2] / fw, b3 = boxes[n*4+3] / fh;
    float G[4] = { b0, b1, b2 - b0, b3 - b1 };
#pragma unroll
    for (int kk = 0; kk < 4; kk++)
        acc += G[kk] * W1[(size_t)(FEATD + kk) * H1DIM + o];
    g_h1[n * H1DIM + o] = acc;
}

// ---------------- K6: per-node per-head attention scores (layer 1) ---------
__global__ void k_score1(const float* __restrict__ a_src,
                         const float* __restrict__ a_dst) {
    int n = blockIdx.x;
    int hd = threadIdx.x >> 5, lane = threadIdx.x & 31;
    float s = 0.f, d = 0.f;
    for (int c = lane; c < GCH; c += 32) {
        float hv = g_h1[n * H1DIM + hd * GCH + c];
        s += hv * a_src[hd * GCH + c];
        d += hv * a_dst[hd * GCH + c];
    }
#pragma unroll
    for (int o = 16; o; o >>= 1) {
        s += __shfl_down_sync(0xffffffffu, s, o);
        d += __shfl_down_sync(0xffffffffu, d, o);
    }
    if (!lane) { g_ss1[n * HEADS + hd] = s; g_ds1[n * HEADS + hd] = d; }
}

// ---------------- K7: GAT1 softmax aggregation + bias + relu ---------------
__global__ void k_gat1(const float* __restrict__ b1) {
    int tnode = blockIdx.x, tid = threadIdx.x;
    int off = g_off[tnode], cnt = g_off[tnode + 1] - off;
    __shared__ float al[E_TOT * HEADS > 4096 ? E_TOT * HEADS : 4096];
    for (int idx = tid; idx < cnt * HEADS; idx += blockDim.x) {
        int k = idx >> 2, hd = idx & 3;
        int sn = g_src[g_inc[off + k]];
        float x = g_ss1[sn * HEADS + hd] + g_ds1[tnode * HEADS + hd];
        al[idx] = (x >= 0.f) ? x : 0.2f * x;   // leaky_relu 0.2
    }
    __syncthreads();
    if (tid < HEADS) {
        float m = -INFINITY;
        for (int k = 0; k < cnt; k++) m = fmaxf(m, al[k * HEADS + tid]);
        float s = 0.f;
        for (int k = 0; k < cnt; k++) { float p = expf(al[k * HEADS + tid] - m); al[k * HEADS + tid] = p; s += p; }
        float inv = 1.f / s;
        for (int k = 0; k < cnt; k++) al[k * HEADS + tid] *= inv;
    }
    __syncthreads();
    for (int o = tid; o < H1DIM; o += blockDim.x) {
        int hd = o >> 8;
        float acc = 0.f;
        for (int k = 0; k < cnt; k++) {
            int sn = g_src[g_inc[off + k]];
            acc += al[k * HEADS + hd] * g_h1[sn * H1DIM + o];
        }
        g_x1[tnode * H1DIM + o] = fmaxf(acc + b1[o], 0.f);
    }
}

// ---------------- K8: h2 = x1 @ W2  (256x1024x21) --------------------------
__global__ void k_gemm2(const float* __restrict__ W2) {
    int n = blockIdx.x;
    int o = threadIdx.x >> 5, lane = threadIdx.x & 31;
    if (o >= OUTD) return;
    float acc = 0.f;
    for (int c = lane; c < H1DIM; c += 32)
        acc += g_x1[n * H1DIM + c] * W2[c * OUTD + o];
#pragma unroll
    for (int s = 16; s; s >>= 1) acc += __shfl_down_sync(0xffffffffu, acc, s);
    if (!lane) g_h2[n * OUTD + o] = acc;
}

// ---------------- K9: layer-2 attention scores -----------------------------
__global__ void k_score2(const float* __restrict__ a_src,
                         const float* __restrict__ a_dst) {
    int n = blockIdx.x * blockDim.x + threadIdx.x;
    if (n >= NN) return;
    float s = 0.f, d = 0.f;
    for (int o = 0; o < OUTD; o++) {
        float hv = g_h2[n * OUTD + o];
        s += hv * a_src[o];
        d += hv * a_dst[o];
    }
    g_ss2[n] = s; g_ds2[n] = d;
}

// ---------------- K10: GAT2 aggregate -> logits + argmax labels ------------
__global__ void k_gat2(const float* __restrict__ b2, float* __restrict__ out,
                       int out_size) {
    int tnode = blockIdx.x, tid = threadIdx.x;   // block of 32
    int off = g_off[tnode], cnt = g_off[tnode + 1] - off;
    __shared__ float al[E_TOT];
    __shared__ float lg[OUTD];
    for (int k = tid; k < cnt; k += 32) {
        int sn = g_src[g_inc[off + k]];
        float x = g_ss2[sn] + g_ds2[tnode];
        al[k] = (x >= 0.f) ? x : 0.2f * x;
    }
    __syncthreads();
    if (tid == 0) {
        float m = -INFINITY;
        for (int k = 0; k < cnt; k++) m = fmaxf(m, al[k]);
        float s = 0.f;
        for (int k = 0; k < cnt; k++) { float p = expf(al[k] - m); al[k] = p; s += p; }
        float inv = 1.f / s;
        for (int k = 0; k < cnt; k++) al[k] *= inv;
    }
    __syncthreads();
    for (int o = tid; o < OUTD; o += 32) {
        float acc = 0.f;
        for (int k = 0; k < cnt; k++) {
            int sn = g_src[g_inc[off + k]];
            acc += al[k] * g_h2[sn * OUTD + o];
        }
        float v = acc + b2[o];
        lg[o] = v;
        out[tnode * OUTD + o] = v;
    }
    __syncthreads();
    if (tid == 0 && out_size >= NN * OUTD + NN) {
        int best = 0;
        float bv = lg[0];
        for (int o = 1; o < OUTD; o++)
            if (lg[o] > bv) { bv = lg[o]; best = o; }   // first max wins (argmax)
        out[NN * OUTD + tnode] = (float)best;
    }
}

// ---------------------------------------------------------------------------
extern "C" void kernel_launch(void* const* d_in, const int* in_sizes, int n_in,
                              void* d_out, int out_size) {
    const float* features = (const float*)d_in[0];
    const float* boxes    = (const float*)d_in[1];
    const float* W_fc1    = (const float*)d_in[2];
    const float* b_fc1    = (const float*)d_in[3];
    const float* W_fc2    = (const float*)d_in[4];
    const float* b_fc2    = (const float*)d_in[5];
    const float* W1       = (const float*)d_in[6];
    const float* a_src1   = (const float*)d_in[7];
    const float* a_dst1   = (const float*)d_in[8];
    const float* b1       = (const float*)d_in[9];
    const float* W2       = (const float*)d_in[10];
    const float* a_src2   = (const float*)d_in[11];
    const float* a_dst2   = (const float*)d_in[12];
    const float* b2       = (const float*)d_in[13];
    const void*  img_h    = d_in[14];
    const void*  img_w    = d_in[15];
    float* out = (float*)d_out;

    dim3 blk16(16, 16);
    k_ab<<<dim3(HIDR / 16, NN / 16, 2), blk16>>>(features, W_fc1);
    k_rel<<<(NN * NN) / 8, 256>>>(boxes, W_fc1, b_fc1, W_fc2, b_fc2);
    k_topk<<<NN, NN>>>();
    k_edges<<<1, NN>>>();
    k_gemm1<<<dim3(H1DIM / 16, NN / 16), blk16>>>(features, boxes, W1, img_h, img_w);
    k_score1<<<NN, 128>>>(a_src1, a_dst1);
    k_gat1<<<NN, 256>>>(b1);
    k_gemm2<<<NN, OUTD * 32>>>(W2);
    k_score2<<<1, NN>>>(a_src2, a_dst2);
    k_gat2<<<NN, 32>>>(b2, out, out_size);
}

// round 2
// speedup vs baseline: 1.2627x; 1.2627x over previous
#include <cuda_runtime.h>
#include <math.h>

#define NN    256
#define FEATD 1024
#define HIDR  256
#define HEADS 4
#define GCH   256
#define H1DIM 1024   // HEADS*GCH
#define OUTD  21
#define TOPK  3
#define E_TOT (NN*TOPK + NN)   // 1024 edges

// ---------------- scratch (device globals; no allocation allowed) ----------
__device__ __align__(16) float g_A[NN*HIDR];
__device__ __align__(16) float g_B[NN*HIDR];
__device__ __align__(16) float g_rel[NN*NN];
__device__ int   g_top[NN*TOPK];
__device__ int   g_src[E_TOT], g_tgt[E_TOT];
__device__ int   g_off[NN+1];
__device__ int   g_inc[E_TOT];
__device__ __align__(16) float g_h1[NN*H1DIM];
__device__ float g_ss1[NN*HEADS], g_ds1[NN*HEADS];
__device__ __align__(16) float g_x1[NN*H1DIM];
__device__ __align__(16) float g_h2[NN*OUTD];
__device__ float g_ss2[NN], g_ds2[NN];

// read a scalar that may have been serialized as int32 or float32
__device__ __forceinline__ float read_dim(const void* p) {
    int iv = *(const int*)p;
    if (iv > 0 && iv < 100000) return (float)iv;
    return *(const float*)p;
}

// ---------------- K1: A = F @ W_fc1[0:1024], B = F @ W_fc1[1024:2048] ------
// Tiled GEMM: BM=32, BN=64, BK=16, 256 thr, 2x4 micro-tile.
// Output cols 0..255 -> g_A (W rows 0..1023), 256..511 -> g_B (W rows 1024..2047)
__global__ void k_ab(const float* __restrict__ feat, const float* __restrict__ Wfc1) {
    __shared__ float  sA[16][33];
    __shared__ float4 sW[16][16];
    int t = threadIdx.x;
    int tx = t & 15, ty = t >> 4;
    int row0 = blockIdx.y * 32;
    int colg = blockIdx.x * 64;
    const float* W;
    float* dst;
    int colL;
    if (colg < 256) { W = Wfc1;                      dst = g_A; colL = colg; }
    else            { W = Wfc1 + (size_t)1024 * HIDR; dst = g_B; colL = colg - 256; }
    float acc[2][4] = {};
    for (int k0 = 0; k0 < FEATD; k0 += 16) {
        if (t < 128) {
            int r = t >> 2, kq = t & 3;
            float4 v = *(const float4*)&feat[(size_t)(row0 + r) * FEATD + k0 + kq * 4];
            sA[kq*4+0][r] = v.x; sA[kq*4+1][r] = v.y; sA[kq*4+2][r] = v.z; sA[kq*4+3][r] = v.w;
        }
        {
            int kr = t >> 4, cq = t & 15;
            sW[kr][cq] = *(const float4*)&W[(size_t)(k0 + kr) * HIDR + colL + cq * 4];
        }
        __syncthreads();
#pragma unroll
        for (int kk = 0; kk < 16; kk++) {
            float a0 = sA[kk][ty], a1 = sA[kk][ty + 16];
            float4 w = sW[kk][tx];
            acc[0][0] += a0 * w.x; acc[0][1] += a0 * w.y; acc[0][2] += a0 * w.z; acc[0][3] += a0 * w.w;
            acc[1][0] += a1 * w.x; acc[1][1] += a1 * w.y; acc[1][2] += a1 * w.z; acc[1][3] += a1 * w.w;
        }
        __syncthreads();
    }
#pragma unroll
    for (int u = 0; u < 2; u++) {
        int r = row0 + ty + u * 16;
        *(float4*)&dst[(size_t)r * HIDR + colL + tx * 4] =
            make_float4(acc[u][0], acc[u][1], acc[u][2], acc[u][3]);
    }
}

// ---------------- K2: rel[i,j] = relu(A[i]+B[j]+bias+geom@Wg) . W_fc2 + b2 -
// Block: 8 i x 64 j, 128 threads, each thread owns 1 i and 4 consecutive j.
__global__ void k_rel(const float* __restrict__ boxes,
                      const float* __restrict__ Wfc1,
                      const float* __restrict__ bfc1,
                      const float* __restrict__ Wfc2,
                      const float* __restrict__ bfc2) {
    __shared__ __align__(16) float sAb[8][HIDR];
    __shared__ __align__(16) float sBt[HIDR][68];   // transposed B tile, stride 68 (16B-aligned rows)
    __shared__ __align__(16) float4 sGeo[HIDR];     // 4 geometry weight rows
    __shared__ float sW2[HIDR];
    int t = threadIdx.x;                 // 128
    int il = t >> 4, jg = t & 15, jl = jg * 4;
    int i0 = blockIdx.y * 8, j0 = blockIdx.x * 64;
    const float* Wg = Wfc1 + (size_t)2 * FEATD * HIDR;
    // load A rows (+bias)
    for (int idx = t; idx < 8 * HIDR; idx += 128) {
        int i = idx >> 8, c = idx & 255;
        sAb[i][c] = g_A[(size_t)(i0 + i) * HIDR + c] + bfc1[c];
    }
    // load B tile transposed
    for (int idx = t; idx < 64 * HIDR; idx += 128) {
        int j = idx >> 8, c = idx & 255;
        sBt[c][j] = g_B[(size_t)(j0 + j) * HIDR + c];
    }
    // geometry weights + W2
    for (int c = t; c < HIDR; c += 128) {
        sGeo[c] = make_float4(Wg[c], Wg[HIDR + c], Wg[2 * HIDR + c], Wg[3 * HIDR + c]);
        sW2[c] = Wfc2[c];
    }
    __syncthreads();
    int ig = i0 + il;
    float bi0 = boxes[ig*4+0], bi1 = boxes[ig*4+1], bi2 = boxes[ig*4+2], bi3 = boxes[ig*4+3];
    float4 G[4];
#pragma unroll
    for (int q = 0; q < 4; q++) {
        int jgl = j0 + jl + q;
        G[q] = make_float4(fabsf(bi0 - boxes[jgl*4+0]), fabsf(bi1 - boxes[jgl*4+1]),
                           fabsf(bi2 - boxes[jgl*4+2]), fabsf(bi3 - boxes[jgl*4+3]));
    }
    float acc[4] = {};
#pragma unroll 4
    for (int c = 0; c < HIDR; c++) {
        float  a  = sAb[il][c];
        float4 wg = sGeo[c];
        float  w2 = sW2[c];
        float4 b4 = *(const float4*)&sBt[c][jl];
        float v0 = a + b4.x + G[0].x*wg.x + G[0].y*wg.y + G[0].z*wg.z + G[0].w*wg.w;
        float v1 = a + b4.y + G[1].x*wg.x + G[1].y*wg.y + G[1].z*wg.z + G[1].w*wg.w;
        float v2 = a + b4.z + G[2].x*wg.x + G[2].y*wg.y + G[2].z*wg.z + G[2].w*wg.w;
        float v3 = a + b4.w + G[3].x*wg.x + G[3].y*wg.y + G[3].z*wg.z + G[3].w*wg.w;
        acc[0] += fmaxf(v0, 0.f) * w2;
        acc[1] += fmaxf(v1, 0.f) * w2;
        acc[2] += fmaxf(v2, 0.f) * w2;
        acc[3] += fmaxf(v3, 0.f) * w2;
    }
    float bb = bfc2[0];
#pragma unroll
    for (int q = 0; q < 4; q++)
        g_rel[(size_t)ig * NN + j0 + jl + q] = acc[q] + bb;
}

// ---------------- K3: per-row top-4, drop first -> g_top[i][0..2] ----------
__global__ void k_topk() {
    int i = blockIdx.x, t = threadIdx.x;
    __shared__ float v[NN];
    __shared__ float rv[NN];
    __shared__ int   ri[NN];
    v[t] = g_rel[i * NN + t];
    __syncthreads();
    for (int sel = 0; sel < TOPK + 1; sel++) {
        rv[t] = v[t]; ri[t] = t;
        __syncthreads();
        for (int s = 128; s; s >>= 1) {
            if (t < s) {
                float a = rv[t], b = rv[t + s];
                if (b > a || (b == a && ri[t + s] < ri[t])) { rv[t] = b; ri[t] = ri[t + s]; }
            }
            __syncthreads();
        }
        int best = ri[0];
        if (sel > 0 && t == 0) g_top[i * TOPK + sel - 1] = best;
        if (t == best) v[t] = -INFINITY;
        __syncthreads();
    }
}

// ---------------- K4: edge list + CSR (fully parallel, stable order) -------
__global__ void k_edges() {
    int t = threadIdx.x;                 // 256 threads, one block
    int lane = t & 31, w = t >> 5;       // 8 warps
    __shared__ int stgt[E_TOT];
    __shared__ int sc[NN];
#pragma unroll
    for (int j = 0; j < TOPK; j++) {
        int tg = g_top[t * TOPK + j];
        g_src[t * TOPK + j] = t;
        g_tgt[t * TOPK + j] = tg;
        stgt[t * TOPK + j] = tg;
    }
    g_src[NN * TOPK + t] = t;
    g_tgt[NN * TOPK + t] = t;
    stgt[NN * TOPK + t] = t;
    __syncthreads();
    // count incoming edges of node t
    int c = 0;
    for (int e = 0; e < E_TOT; e++) c += (stgt[e] == t);
    sc[t] = c;
    __syncthreads();
    // inclusive scan (Hillis-Steele)
    for (int s = 1; s < NN; s <<= 1) {
        int v = (t >= s) ? sc[t - s] : 0;
        __syncthreads();
        sc[t] += v;
        __syncthreads();
    }
    g_off[t + 1] = sc[t];
    if (t == 0) g_off[0] = 0;
    __syncthreads();
    // stable bucket fill via warp ballot, in ascending edge-index order
    for (int n = w; n < NN; n += 8) {
        int base = (n == 0) ? 0 : sc[n - 1];
        int run = 0;
        for (int e0 = 0; e0 < E_TOT; e0 += 32) {
            int e = e0 + lane;
            bool hit = (stgt[e] == n);
            unsigned m = __ballot_sync(0xffffffffu, hit);
            if (hit) {
                int p = run + __popc(m & ((1u << lane) - 1u));
                g_inc[base + p] = e;
            }
            run += __popc(m);
        }
    }
}

// ---------------- K5: h1 = [features | geomn] @ W1 (tiled GEMM) ------------
__global__ void k_gemm1(const float* __restrict__ feat,
                        const float* __restrict__ boxes,
                        const float* __restrict__ W1,
                        const void* img_h, const void* img_w) {
    __shared__ float  sA[16][33];
    __shared__ float4 sW[16][16];
    int t = threadIdx.x;
    int tx = t & 15, ty = t >> 4;
    int row0 = blockIdx.y * 32;
    int col0 = blockIdx.x * 64;
    float acc[2][4] = {};
    for (int k0 = 0; k0 < FEATD; k0 += 16) {
        if (t < 128) {
            int r = t >> 2, kq = t & 3;
            float4 v = *(const float4*)&feat[(size_t)(row0 + r) * FEATD + k0 + kq * 4];
            sA[kq*4+0][r] = v.x; sA[kq*4+1][r] = v.y; sA[kq*4+2][r] = v.z; sA[kq*4+3][r] = v.w;
        }
        {
            int kr = t >> 4, cq = t & 15;
            sW[kr][cq] = *(const float4*)&W1[(size_t)(k0 + kr) * H1DIM + col0 + cq * 4];
        }
        __syncthreads();
#pragma unroll
        for (int kk = 0; kk < 16; kk++) {
            float a0 = sA[kk][ty], a1 = sA[kk][ty + 16];
            float4 w = sW[kk][tx];
            acc[0][0] += a0 * w.x; acc[0][1] += a0 * w.y; acc[0][2] += a0 * w.z; acc[0][3] += a0 * w.w;
            acc[1][0] += a1 * w.x; acc[1][1] += a1 * w.y; acc[1][2] += a1 * w.z; acc[1][3] += a1 * w.w;
        }
        __syncthreads();
    }
    float fw = read_dim(img_w), fh = read_dim(img_h);
#pragma unroll
    for (int u = 0; u < 2; u++) {
        int n = row0 + ty + u * 16;
        float b0 = boxes[n*4+0] / fw, b1 = boxes[n*4+1] / fh;
        float b2 = boxes[n*4+2] / fw, b3 = boxes[n*4+3] / fh;
        float G[4] = { b0, b1, b2 - b0, b3 - b1 };
#pragma unroll
        for (int kk = 0; kk < 4; kk++) {
            const float* wr = &W1[(size_t)(FEATD + kk) * H1DIM + col0 + tx * 4];
            acc[u][0] += G[kk] * wr[0];
            acc[u][1] += G[kk] * wr[1];
            acc[u][2] += G[kk] * wr[2];
            acc[u][3] += G[kk] * wr[3];
        }
        *(float4*)&g_h1[(size_t)n * H1DIM + col0 + tx * 4] =
            make_float4(acc[u][0], acc[u][1], acc[u][2], acc[u][3]);
    }
}

// ---------------- K6: per-node per-head attention scores (layer 1) ---------
__global__ void k_score1(const float* __restrict__ a_src,
                         const float* __restrict__ a_dst) {
    int n = blockIdx.x;
    int hd = threadIdx.x >> 5, lane = threadIdx.x & 31;
    float s = 0.f, d = 0.f;
    for (int c = lane; c < GCH; c += 32) {
        float hv = g_h1[n * H1DIM + hd * GCH + c];
        s += hv * a_src[hd * GCH + c];
        d += hv * a_dst[hd * GCH + c];
    }
#pragma unroll
    for (int o = 16; o; o >>= 1) {
        s += __shfl_down_sync(0xffffffffu, s, o);
        d += __shfl_down_sync(0xffffffffu, d, o);
    }
    if (!lane) { g_ss1[n * HEADS + hd] = s; g_ds1[n * HEADS + hd] = d; }
}

// ---------------- K7: GAT1 softmax aggregation + bias + relu ---------------
__global__ void k_gat1(const float* __restrict__ b1) {
    int tnode = blockIdx.x, tid = threadIdx.x;
    int off = g_off[tnode], cnt = g_off[tnode + 1] - off;
    __shared__ float al[E_TOT * HEADS > 4096 ? E_TOT * HEADS : 4096];
    for (int idx = tid; idx < cnt * HEADS; idx += blockDim.x) {
        int k = idx >> 2, hd = idx & 3;
        int sn = g_src[g_inc[off + k]];
        float x = g_ss1[sn * HEADS + hd] + g_ds1[tnode * HEADS + hd];
        al[idx] = (x >= 0.f) ? x : 0.2f * x;   // leaky_relu 0.2
    }
    __syncthreads();
    if (tid < HEADS) {
        float m = -INFINITY;
        for (int k = 0; k < cnt; k++) m = fmaxf(m, al[k * HEADS + tid]);
        float s = 0.f;
        for (int k = 0; k < cnt; k++) { float p = expf(al[k * HEADS + tid] - m); al[k * HEADS + tid] = p; s += p; }
        float inv = 1.f / s;
        for (int k = 0; k < cnt; k++) al[k * HEADS + tid] *= inv;
    }
    __syncthreads();
    for (int o = tid; o < H1DIM; o += blockDim.x) {
        int hd = o >> 8;
        float acc = 0.f;
        for (int k = 0; k < cnt; k++) {
            int sn = g_src[g_inc[off + k]];
            acc += al[k * HEADS + hd] * g_h1[sn * H1DIM + o];
        }
        g_x1[tnode * H1DIM + o] = fmaxf(acc + b1[o], 0.f);
    }
}

// ---------------- K8: h2 = x1 @ W2 + layer-2 attention scores --------------
__global__ void k_gemm2(const float* __restrict__ W2,
                        const float* __restrict__ a_src,
                        const float* __restrict__ a_dst) {
    int n = blockIdx.x;
    int o = threadIdx.x >> 5, lane = threadIdx.x & 31;
    __shared__ float lg[OUTD];
    if (o < OUTD) {
        float acc = 0.f;
        for (int c = lane; c < H1DIM; c += 32)
            acc += g_x1[n * H1DIM + c] * W2[c * OUTD + o];
#pragma unroll
        for (int s = 16; s; s >>= 1) acc += __shfl_down_sync(0xffffffffu, acc, s);
        if (!lane) { g_h2[n * OUTD + o] = acc; lg[o] = acc; }
    }
    __syncthreads();
    if (threadIdx.x == 0) {
        float s = 0.f, d = 0.f;
        for (int oo = 0; oo < OUTD; oo++) {
            s += lg[oo] * a_src[oo];
            d += lg[oo] * a_dst[oo];
        }
        g_ss2[n] = s; g_ds2[n] = d;
    }
}

// ---------------- K10: GAT2 aggregate -> logits + argmax labels ------------
__global__ void k_gat2(const float* __restrict__ b2, float* __restrict__ out,
                       int out_size) {
    int tnode = blockIdx.x, tid = threadIdx.x;   // block of 32
    int off = g_off[tnode], cnt = g_off[tnode + 1] - off;
    __shared__ float al[E_TOT];
    __shared__ float lg[OUTD];
    for (int k = tid; k < cnt; k += 32) {
        int sn = g_src[g_inc[off + k]];
        float x = g_ss2[sn] + g_ds2[tnode];
        al[k] = (x >= 0.f) ? x : 0.2f * x;
    }
    __syncthreads();
    if (tid == 0) {
        float m = -INFINITY;
        for (int k = 0; k < cnt; k++) m = fmaxf(m, al[k]);
        float s = 0.f;
        for (int k = 0; k < cnt; k++) { float p = expf(al[k] - m); al[k] = p; s += p; }
        float inv = 1.f / s;
        for (int k = 0; k < cnt; k++) al[k] *= inv;
    }
    __syncthreads();
    for (int o = tid; o < OUTD; o += 32) {
        float acc = 0.f;
        for (int k = 0; k < cnt; k++) {
            int sn = g_src[g_inc[off + k]];
            acc += al[k] * g_h2[sn * OUTD + o];
        }
        float v = acc + b2[o];
        lg[o] = v;
        out[tnode * OUTD + o] = v;
    }
    __syncthreads();
    if (tid == 0 && out_size >= NN * OUTD + NN) {
        int best = 0;
        float bv = lg[0];
        for (int o = 1; o < OUTD; o++)
            if (lg[o] > bv) { bv = lg[o]; best = o; }
        out[NN * OUTD + tnode] = (float)best;
    }
}

// ---------------------------------------------------------------------------
extern "C" void kernel_launch(void* const* d_in, const int* in_sizes, int n_in,
                              void* d_out, int out_size) {
    const float* features = (const float*)d_in[0];
    const float* boxes    = (const float*)d_in[1];
    const float* W_fc1    = (const float*)d_in[2];
    const float* b_fc1    = (const float*)d_in[3];
    const float* W_fc2    = (const float*)d_in[4];
    const float* b_fc2    = (const float*)d_in[5];
    const float* W1       = (const float*)d_in[6];
    const float* a_src1   = (const float*)d_in[7];
    const float* a_dst1   = (const float*)d_in[8];
    const float* b1       = (const float*)d_in[9];
    const float* W2       = (const float*)d_in[10];
    const float* a_src2   = (const float*)d_in[11];
    const float* a_dst2   = (const float*)d_in[12];
    const float* b2       = (const float*)d_in[13];
    const void*  img_h    = d_in[14];
    const void*  img_w    = d_in[15];
    float* out = (float*)d_out;

    k_ab<<<dim3(8, 8), 256>>>(features, W_fc1);
    k_rel<<<dim3(4, 32), 128>>>(boxes, W_fc1, b_fc1, W_fc2, b_fc2);
    k_topk<<<NN, NN>>>();
    k_edges<<<1, NN>>>();
    k_gemm1<<<dim3(16, 8), 256>>>(features, boxes, W1, img_h, img_w);
    k_score1<<<NN, 128>>>(a_src1, a_dst1);
    k_gat1<<<NN, 256>>>(b1);
    k_gemm2<<<NN, OUTD * 32>>>(W2, a_src2, a_dst2);
    k_gat2<<<NN, 32>>>(b2, out, out_size);
}